// round 5
// baseline (speedup 1.0000x reference)
#include <cuda_runtime.h>

#define NN   50000
#define EE   800000
#define NG   500
#define C    100
#define KIN  33
#define OUTC 200
#define BN_EPS 1e-5f

// ---------------- scratch (device globals; no allocations) ----------------
__device__ int    d_fmt64;
__device__ int    d_src[EE];
__device__ int    d_dst[EE];
__device__ int    d_batch[NN];
__device__ int    d_indeg[NN];
__device__ int    d_row[NN + 1];
__device__ int    d_cursor[NN];
__device__ unsigned long long d_e[EE];       // packed {w_bits<<32 | src}
__device__ float  d_dinv[NN];
__device__ int    d_gstart[NG + 1];
__device__ float  d_aggx[NN * KIN];          // aggregated input features
__device__ __align__(16) float  d_m[NN * C];
__device__ __align__(16) float  d_agg[NN * C];
__device__ float  d_bs[C];                   // BN sum accumulators
__device__ float  d_bq[C];                   // BN sumsq accumulators
__device__ __align__(16) float  d_scale[C];
__device__ __align__(16) float  d_shift[C];

// ---------------- input decode ----------------
__global__ void k_detect(const long long* __restrict__ ei) {
    int ok = 1;
    for (int i = 0; i < 64; i++) {
        long long v = ei[i];
        if (v < 0 || v >= NN) { ok = 0; break; }
    }
    d_fmt64 = ok;
}

// convert edges + count in-degree in one pass
__global__ void k_prep_edges(const void* __restrict__ eiv) {
    int e = blockIdx.x * blockDim.x + threadIdx.x;
    if (e >= EE) return;
    int s, d;
    if (d_fmt64) {
        const long long* p = (const long long*)eiv;
        s = (int)p[e]; d = (int)p[EE + e];
    } else {
        const int* p = (const int*)eiv;
        s = p[e]; d = p[EE + e];
    }
    if ((unsigned)s >= NN) s = 0;
    if ((unsigned)d >= NN) d = 0;
    d_src[e] = s;
    d_dst[e] = d;
    atomicAdd(&d_indeg[d], 1);
}

__global__ void k_indeg_zero() {
    int i = blockIdx.x * blockDim.x + threadIdx.x;
    if (i < NN) d_indeg[i] = 0;
}

__global__ void k_convert_batch(const void* __restrict__ bv) {
    int i = blockIdx.x * blockDim.x + threadIdx.x;
    if (i >= NN) return;
    int g;
    if (d_fmt64) g = (int)((const long long*)bv)[i];
    else         g = ((const int*)bv)[i];
    if ((unsigned)g >= NG) g = 0;
    d_batch[i] = g;
}

// single-block scan: row_ptr + cursor
__global__ void k_scan() {
    __shared__ int part[1024];
    const int t = threadIdx.x;
    const int per = (NN + 1023) / 1024;
    const int base = t * per;
    int s = 0;
    for (int i = 0; i < per; i++) {
        int idx = base + i;
        if (idx < NN) s += d_indeg[idx];
    }
    part[t] = s;
    __syncthreads();
    for (int off = 1; off < 1024; off <<= 1) {
        int v = (t >= off) ? part[t - off] : 0;
        __syncthreads();
        part[t] += v;
        __syncthreads();
    }
    int run = (t > 0) ? part[t - 1] : 0;
    for (int i = 0; i < per; i++) {
        int idx = base + i;
        if (idx < NN) {
            d_row[idx] = run;
            d_cursor[idx] = run;
            run += d_indeg[idx];
        }
    }
    if (t == 0) d_row[NN] = EE;
}

__global__ void k_dinv() {
    int i = blockIdx.x * blockDim.x + threadIdx.x;
    if (i < NN) d_dinv[i] = rsqrtf((float)(d_indeg[i] + 1));
    if (i < C) { d_bs[i] = 0.0f; d_bq[i] = 0.0f; }
}

__global__ void k_fill() {
    int e = blockIdx.x * blockDim.x + threadIdx.x;
    if (e < EE) {
        int s = d_src[e], d = d_dst[e];
        int p = atomicAdd(&d_cursor[d], 1);
        float w = d_dinv[s] * d_dinv[d];
        d_e[p] = ((unsigned long long)__float_as_uint(w) << 32) | (unsigned)s;
    }
}

__global__ void k_bounds() {
    int g = blockIdx.x * blockDim.x + threadIdx.x;
    if (g > NG) return;
    int lo = 0, hi = NN;
    while (lo < hi) {
        int mid = (lo + hi) >> 1;
        if (d_batch[mid] < g) lo = mid + 1; else hi = mid;
    }
    d_gstart[g] = lo;
}

// ---------------- layer-0 gather on raw x (33 ch): aggx = dinv^2 x + sum w x[src] ----
__global__ void k_gatherX(const float* __restrict__ x) {
    int warp = (blockIdx.x * blockDim.x + threadIdx.x) >> 5;
    int lane = threadIdx.x & 31;
    if (warp >= NN) return;
    const int beg = d_row[warp], end = d_row[warp + 1];
    float dv = d_dinv[warp];
    float d2 = dv * dv;
    float a0 = d2 * x[(size_t)warp * KIN + lane];
    float a1 = (lane == 0) ? d2 * x[(size_t)warp * KIN + 32] : 0.0f;
    int e = beg;
    for (; e + 1 < end; e += 2) {
        unsigned long long v0 = d_e[e], v1 = d_e[e + 1];
        int s0 = (int)(unsigned)v0, s1 = (int)(unsigned)v1;
        float w0 = __uint_as_float((unsigned)(v0 >> 32));
        float w1 = __uint_as_float((unsigned)(v1 >> 32));
        float x0 = x[(size_t)s0 * KIN + lane];
        float x1 = x[(size_t)s1 * KIN + lane];
        a0 = fmaf(w0, x0, a0);
        a0 = fmaf(w1, x1, a0);
        if (lane == 0) {
            a1 = fmaf(w0, x[(size_t)s0 * KIN + 32], a1);
            a1 = fmaf(w1, x[(size_t)s1 * KIN + 32], a1);
        }
    }
    if (e < end) {
        unsigned long long v0 = d_e[e];
        int s0 = (int)(unsigned)v0;
        float w0 = __uint_as_float((unsigned)(v0 >> 32));
        a0 = fmaf(w0, x[(size_t)s0 * KIN + lane], a0);
        if (lane == 0) a1 = fmaf(w0, x[(size_t)s0 * KIN + 32], a1);
    }
    d_aggx[(size_t)warp * KIN + lane] = a0;
    if (lane == 0) d_aggx[(size_t)warp * KIN + 32] = a1;
}

// ---------------- GEMM ----------------
// mode 1 (layer 0): in = d_aggx (K=33), out = acc + b -> d_agg, fused BN stats
// mode 0 (layers 1-3): in = BN(d_agg)+ReLU (K=100), out = acc -> d_m
#define MT 64
#define KC 50
__global__ void k_gemm(const float* __restrict__ W,
                       const float* __restrict__ bvec,
                       int K, int mode)
{
    __shared__ __align__(16) float Ws[KC][C];
    __shared__ __align__(16) float Hst[KC][MT];
    __shared__ float red_s[8][C];
    __shared__ float red_q[8][C];

    const int tx  = threadIdx.x;          // 0..24
    const int ty  = threadIdx.y;          // 0..7
    const int tid = ty * 25 + tx;
    const int r0b = blockIdx.x * MT;

    float acc[8][4];
#pragma unroll
    for (int i = 0; i < 8; i++)
#pragma unroll
        for (int j = 0; j < 4; j++) acc[i][j] = 0.0f;

    for (int k0 = 0; k0 < K; k0 += KC) {
        const int kc = min(KC, K - k0);
        for (int idx = tid; idx < kc * C; idx += 200) {
            int kk = idx / C, cc = idx - kk * C;
            Ws[kk][cc] = W[(size_t)(k0 + kk) * C + cc];
        }
        for (int idx = tid; idx < MT * kc; idx += 200) {
            int rr = idx / kc, kk = idx - rr * kc;
            int r = r0b + rr;
            float v = 0.0f;
            if (r < NN) {
                int ch = k0 + kk;
                if (mode) {
                    v = d_aggx[(size_t)r * KIN + ch];
                } else {
                    v = d_agg[(size_t)r * C + ch];
                    v = fmaxf(fmaf(v, d_scale[ch], d_shift[ch]), 0.0f);
                }
            }
            Hst[kk][rr] = v;
        }
        __syncthreads();

#pragma unroll 2
        for (int k = 0; k < kc; k++) {
            float4 w4 = *(const float4*)&Ws[k][tx * 4];
            float4 h0 = *(const float4*)&Hst[k][ty * 8];
            float4 h1 = *(const float4*)&Hst[k][ty * 8 + 4];
            float hv[8] = {h0.x, h0.y, h0.z, h0.w, h1.x, h1.y, h1.z, h1.w};
#pragma unroll
            for (int i = 0; i < 8; i++) {
                acc[i][0] = fmaf(hv[i], w4.x, acc[i][0]);
                acc[i][1] = fmaf(hv[i], w4.y, acc[i][1]);
                acc[i][2] = fmaf(hv[i], w4.z, acc[i][2]);
                acc[i][3] = fmaf(hv[i], w4.w, acc[i][3]);
            }
        }
        __syncthreads();
    }

    const int c0 = tx * 4;
    if (mode) {
        // layer 0: add bias, write d_agg, fused BN stats
        const float4 b4 = *(const float4*)&bvec[c0];
        float s[4] = {0, 0, 0, 0}, q[4] = {0, 0, 0, 0};
#pragma unroll
        for (int i = 0; i < 8; i++) {
            int r = r0b + ty * 8 + i;
            if (r < NN) {
                float4 v = make_float4(acc[i][0] + b4.x, acc[i][1] + b4.y,
                                       acc[i][2] + b4.z, acc[i][3] + b4.w);
                *(float4*)&d_agg[(size_t)r * C + c0] = v;
                s[0] += v.x; s[1] += v.y; s[2] += v.z; s[3] += v.w;
                q[0] = fmaf(v.x, v.x, q[0]); q[1] = fmaf(v.y, v.y, q[1]);
                q[2] = fmaf(v.z, v.z, q[2]); q[3] = fmaf(v.w, v.w, q[3]);
            }
        }
#pragma unroll
        for (int j = 0; j < 4; j++) { red_s[ty][c0 + j] = s[j]; red_q[ty][c0 + j] = q[j]; }
        __syncthreads();
        if (tid < C) {
            float S = 0.0f, Q = 0.0f;
#pragma unroll
            for (int t = 0; t < 8; t++) { S += red_s[t][tid]; Q += red_q[t][tid]; }
            atomicAdd(&d_bs[tid], S);
            atomicAdd(&d_bq[tid], Q);
        }
    } else {
#pragma unroll
        for (int i = 0; i < 8; i++) {
            int r = r0b + ty * 8 + i;
            if (r < NN)
                *(float4*)&d_m[(size_t)r * C + c0] =
                    make_float4(acc[i][0], acc[i][1], acc[i][2], acc[i][3]);
        }
    }
}

// ---------------- gather (layers 1-3): agg = dinv^2 m + b + sum w m[src]; fused stats ----
__global__ void k_gather(const float* __restrict__ bvec) {
    __shared__ float ss[8][C];
    __shared__ float sq[8][C];
    const int w8   = threadIdx.x >> 5;
    const int lane = threadIdx.x & 31;
    const int node = blockIdx.x * 8 + w8;

    float4 acc = make_float4(0.f, 0.f, 0.f, 0.f);
    const bool active = (node < NN) && (lane < 25);
    if (node < NN) {
        const int beg = d_row[node], end = d_row[node + 1];
        if (active) {
            float dv = d_dinv[node];
            float d2 = dv * dv;
            const float4 mv = *(const float4*)&d_m[(size_t)node * C + lane * 4];
            const float4 b4 = *(const float4*)&bvec[lane * 4];
            acc = make_float4(fmaf(d2, mv.x, b4.x), fmaf(d2, mv.y, b4.y),
                              fmaf(d2, mv.z, b4.z), fmaf(d2, mv.w, b4.w));
        }
        int e = beg;
        for (; e + 1 < end; e += 2) {
            unsigned long long v0 = d_e[e], v1 = d_e[e + 1];
            int s0 = (int)(unsigned)v0, s1 = (int)(unsigned)v1;
            float w0 = __uint_as_float((unsigned)(v0 >> 32));
            float w1 = __uint_as_float((unsigned)(v1 >> 32));
            if (active) {
                const float4 a0 = *(const float4*)&d_m[(size_t)s0 * C + lane * 4];
                const float4 a1 = *(const float4*)&d_m[(size_t)s1 * C + lane * 4];
                acc.x = fmaf(w0, a0.x, acc.x); acc.y = fmaf(w0, a0.y, acc.y);
                acc.z = fmaf(w0, a0.z, acc.z); acc.w = fmaf(w0, a0.w, acc.w);
                acc.x = fmaf(w1, a1.x, acc.x); acc.y = fmaf(w1, a1.y, acc.y);
                acc.z = fmaf(w1, a1.z, acc.z); acc.w = fmaf(w1, a1.w, acc.w);
            }
        }
        if (e < end) {
            unsigned long long v0 = d_e[e];
            int s0 = (int)(unsigned)v0;
            float w0 = __uint_as_float((unsigned)(v0 >> 32));
            if (active) {
                const float4 a0 = *(const float4*)&d_m[(size_t)s0 * C + lane * 4];
                acc.x = fmaf(w0, a0.x, acc.x); acc.y = fmaf(w0, a0.y, acc.y);
                acc.z = fmaf(w0, a0.z, acc.z); acc.w = fmaf(w0, a0.w, acc.w);
            }
        }
        if (active) *(float4*)&d_agg[(size_t)node * C + lane * 4] = acc;
    }
    // fused BN stats
    if (lane < 25) {
        int c = lane * 4;
        if (active) {
            ss[w8][c]     = acc.x; ss[w8][c + 1] = acc.y;
            ss[w8][c + 2] = acc.z; ss[w8][c + 3] = acc.w;
            sq[w8][c]     = acc.x * acc.x; sq[w8][c + 1] = acc.y * acc.y;
            sq[w8][c + 2] = acc.z * acc.z; sq[w8][c + 3] = acc.w * acc.w;
        } else {
            ss[w8][c] = ss[w8][c + 1] = ss[w8][c + 2] = ss[w8][c + 3] = 0.0f;
            sq[w8][c] = sq[w8][c + 1] = sq[w8][c + 2] = sq[w8][c + 3] = 0.0f;
        }
    }
    __syncthreads();
    if (threadIdx.x < C) {
        float S = 0.0f, Q = 0.0f;
#pragma unroll
        for (int t = 0; t < 8; t++) { S += ss[t][threadIdx.x]; Q += sq[t][threadIdx.x]; }
        atomicAdd(&d_bs[threadIdx.x], S);
        atomicAdd(&d_bq[threadIdx.x], Q);
    }
}

// ---------------- finalize BN: scale/shift, reset accumulators ----------------
__global__ void k_finalize(const float* __restrict__ gamma,
                           const float* __restrict__ beta) {
    int c = threadIdx.x;
    if (c >= C) return;
    float mean = d_bs[c] * (1.0f / (float)NN);
    float var  = d_bq[c] * (1.0f / (float)NN) - mean * mean;
    float rstd = rsqrtf(var + BN_EPS);
    float sc = rstd * gamma[c];
    d_scale[c] = sc;
    d_shift[c] = beta[c] - mean * sc;
    d_bs[c] = 0.0f;
    d_bq[c] = 0.0f;
}

// ---------------- fused pool + output head ----------------
__global__ void k_poolout(const float* __restrict__ Wout,
                          const float* __restrict__ bout,
                          float* __restrict__ out) {
    __shared__ float pool[C];
    const int g = blockIdx.x;
    const int t = threadIdx.x;        // 0..199
    const int r0 = d_gstart[g], r1 = d_gstart[g + 1];
    if (t < C) {
        float s = 0.0f;
        for (int r = r0; r < r1; r++) s += d_agg[(size_t)r * C + t];
        pool[t] = fmaf(d_scale[t], s, (float)(r1 - r0) * d_shift[t]);
    }
    __syncthreads();
    float acc = bout[t];
#pragma unroll 4
    for (int k = 0; k < C; k++)
        acc = fmaf(pool[k], Wout[(size_t)k * OUTC + t], acc);
    out[(size_t)g * OUTC + t] = acc > 0.0f ? acc : 0.1f * acc;
}

// ---------------- launch ----------------
extern "C" void kernel_launch(void* const* d_in, const int* in_sizes, int n_in,
                              void* d_out, int out_size) {
    const float *x = 0, *W0 = 0, *Wrest = 0, *bb = 0, *gamma = 0, *beta = 0,
                *Wout = 0, *bout = 0;
    const void *ei = 0, *batch = 0;
    for (int i = 0; i < n_in; i++) {
        switch (in_sizes[i]) {
            case 1650000: x     = (const float*)d_in[i]; break;
            case 1600000: ei    = d_in[i];               break;
            case 50000:   batch = d_in[i];               break;
            case 3300:    W0    = (const float*)d_in[i]; break;
            case 30000:   Wrest = (const float*)d_in[i]; break;
            case 20000:   Wout  = (const float*)d_in[i]; break;
            case 200:     bout  = (const float*)d_in[i]; break;
            case 400:
                if (!bb) bb = (const float*)d_in[i];
                else if (!gamma) gamma = (const float*)d_in[i];
                else beta = (const float*)d_in[i];
                break;
            default: break;
        }
    }
    if (!x)     x     = (const float*)d_in[0];
    if (!ei)    ei    = d_in[1];
    if (!batch) batch = d_in[2];
    if (!W0)    W0    = (const float*)d_in[3];
    if (!Wrest) Wrest = (const float*)d_in[4];
    if (!bb)    bb    = (const float*)d_in[5];
    if (!gamma) gamma = (const float*)d_in[6];
    if (!beta)  beta  = (const float*)d_in[7];
    if (!Wout)  Wout  = (const float*)d_in[8];
    if (!bout)  bout  = (const float*)d_in[9];
    float* out = (float*)d_out;

    k_detect<<<1, 1>>>((const long long*)ei);
    k_indeg_zero<<<(NN + 255) / 256, 256>>>();
    k_prep_edges<<<(EE + 255) / 256, 256>>>(ei);
    k_convert_batch<<<(NN + 255) / 256, 256>>>(batch);
    k_scan<<<1, 1024>>>();
    k_dinv<<<(NN + 255) / 256, 256>>>();
    k_fill<<<(EE + 255) / 256, 256>>>();
    k_bounds<<<2, 512>>>();

    const dim3 gemm_blk(25, 8);
    const int gemm_grid = (NN + MT - 1) / MT;
    const int gather_grid = (NN + 7) / 8;          // 8 warps/block, 1 node/warp

    // layer 0: aggregate x first, then GEMM (+bias, +stats)
    k_gatherX<<<(NN * 32 + 255) / 256, 256>>>(x);
    k_gemm<<<gemm_grid, gemm_blk>>>(W0, bb, KIN, 1);
    k_finalize<<<1, 128>>>(gamma, beta);

    // layers 1-3
    for (int L = 1; L < 4; L++) {
        const float* W = Wrest + (size_t)(L - 1) * C * C;
        k_gemm<<<gemm_grid, gemm_blk>>>(W, 0, C, 0);
        k_gather<<<gather_grid, 256>>>(bb + L * C);
        k_finalize<<<1, 128>>>(gamma + L * C, beta + L * C);
    }

    k_poolout<<<NG, OUTC>>>(Wout, bout, out);
}

// round 6
// speedup vs baseline: 1.0898x; 1.0898x over previous
#include <cuda_runtime.h>

#define NN   50000
#define EE   800000
#define NG   500
#define C    100
#define KIN  33
#define OUTC 200
#define BN_EPS 1e-5f

// ---------------- scratch (device globals; no allocations) ----------------
__device__ int    d_fmt64;
__device__ int    d_src[EE];
__device__ int    d_dst[EE];
__device__ int    d_batch[NN];
__device__ int    d_indeg[NN];
__device__ int    d_row[NN + 1];
__device__ int    d_cursor[NN];
__device__ unsigned long long d_e[EE];       // packed {w_bits<<32 | src}
__device__ float  d_dinv[NN];
__device__ int    d_gstart[NG + 1];
__device__ float  d_aggx[NN * KIN];
__device__ __align__(16) float  d_m[NN * C];
__device__ __align__(16) float  d_agg[NN * C];
#define SGRID 98            // ceil(NN / 512)
__device__ float  d_psum[SGRID * C];
__device__ float  d_psq[SGRID * C];
__device__ __align__(16) float  d_scale[C];
__device__ __align__(16) float  d_shift[C];

// ---------------- input decode ----------------
__global__ void k_detect(const long long* __restrict__ ei) {
    int ok = 1;
    for (int i = 0; i < 64; i++) {
        long long v = ei[i];
        if (v < 0 || v >= NN) { ok = 0; break; }
    }
    d_fmt64 = ok;
}

__global__ void k_indeg_zero() {
    int i = blockIdx.x * blockDim.x + threadIdx.x;
    if (i < NN) d_indeg[i] = 0;
}

__global__ void k_prep_edges(const void* __restrict__ eiv) {
    int e = blockIdx.x * blockDim.x + threadIdx.x;
    if (e >= EE) return;
    int s, d;
    if (d_fmt64) {
        const long long* p = (const long long*)eiv;
        s = (int)p[e]; d = (int)p[EE + e];
    } else {
        const int* p = (const int*)eiv;
        s = p[e]; d = p[EE + e];
    }
    if ((unsigned)s >= NN) s = 0;
    if ((unsigned)d >= NN) d = 0;
    d_src[e] = s;
    d_dst[e] = d;
    atomicAdd(&d_indeg[d], 1);
}

__global__ void k_convert_batch(const void* __restrict__ bv) {
    int i = blockIdx.x * blockDim.x + threadIdx.x;
    if (i >= NN) return;
    int g;
    if (d_fmt64) g = (int)((const long long*)bv)[i];
    else         g = ((const int*)bv)[i];
    if ((unsigned)g >= NG) g = 0;
    d_batch[i] = g;
}

__global__ void k_scan() {
    __shared__ int part[1024];
    const int t = threadIdx.x;
    const int per = (NN + 1023) / 1024;
    const int base = t * per;
    int s = 0;
    for (int i = 0; i < per; i++) {
        int idx = base + i;
        if (idx < NN) s += d_indeg[idx];
    }
    part[t] = s;
    __syncthreads();
    for (int off = 1; off < 1024; off <<= 1) {
        int v = (t >= off) ? part[t - off] : 0;
        __syncthreads();
        part[t] += v;
        __syncthreads();
    }
    int run = (t > 0) ? part[t - 1] : 0;
    for (int i = 0; i < per; i++) {
        int idx = base + i;
        if (idx < NN) {
            d_row[idx] = run;
            d_cursor[idx] = run;
            run += d_indeg[idx];
        }
    }
    if (t == 0) d_row[NN] = EE;
}

__global__ void k_dinv() {
    int i = blockIdx.x * blockDim.x + threadIdx.x;
    if (i < NN) d_dinv[i] = rsqrtf((float)(d_indeg[i] + 1));
}

__global__ void k_fill() {
    int e = blockIdx.x * blockDim.x + threadIdx.x;
    if (e < EE) {
        int s = d_src[e], d = d_dst[e];
        int p = atomicAdd(&d_cursor[d], 1);
        float w = d_dinv[s] * d_dinv[d];
        d_e[p] = ((unsigned long long)__float_as_uint(w) << 32) | (unsigned)s;
    }
}

__global__ void k_bounds() {
    int g = blockIdx.x * blockDim.x + threadIdx.x;
    if (g > NG) return;
    int lo = 0, hi = NN;
    while (lo < hi) {
        int mid = (lo + hi) >> 1;
        if (d_batch[mid] < g) lo = mid + 1; else hi = mid;
    }
    d_gstart[g] = lo;
}

// ---------------- layer-0 gather on raw x (independent warps) ----------------
__global__ void k_gatherX(const float* __restrict__ x) {
    int warp = (blockIdx.x * blockDim.x + threadIdx.x) >> 5;
    int lane = threadIdx.x & 31;
    if (warp >= NN) return;
    const int beg = d_row[warp], end = d_row[warp + 1];
    float dv = d_dinv[warp];
    float d2 = dv * dv;
    float a0 = d2 * x[(size_t)warp * KIN + lane];
    float a1 = (lane == 0) ? d2 * x[(size_t)warp * KIN + 32] : 0.0f;
    int e = beg;
    for (; e + 1 < end; e += 2) {
        unsigned long long v0 = d_e[e], v1 = d_e[e + 1];
        int s0 = (int)(unsigned)v0, s1 = (int)(unsigned)v1;
        float w0 = __uint_as_float((unsigned)(v0 >> 32));
        float w1 = __uint_as_float((unsigned)(v1 >> 32));
        float x0 = x[(size_t)s0 * KIN + lane];
        float x1 = x[(size_t)s1 * KIN + lane];
        a0 = fmaf(w0, x0, a0);
        a0 = fmaf(w1, x1, a0);
        if (lane == 0) {
            a1 = fmaf(w0, x[(size_t)s0 * KIN + 32], a1);
            a1 = fmaf(w1, x[(size_t)s1 * KIN + 32], a1);
        }
    }
    if (e < end) {
        unsigned long long v0 = d_e[e];
        int s0 = (int)(unsigned)v0;
        float w0 = __uint_as_float((unsigned)(v0 >> 32));
        a0 = fmaf(w0, x[(size_t)s0 * KIN + lane], a0);
        if (lane == 0) a1 = fmaf(w0, x[(size_t)s0 * KIN + 32], a1);
    }
    d_aggx[(size_t)warp * KIN + lane] = a0;
    if (lane == 0) d_aggx[(size_t)warp * KIN + 32] = a1;
}

// ---------------- GEMM (round-4 layout, known good) ----------------
// mode 1 (layer 0): in = d_aggx (K=33), out = acc + b -> d_agg
// mode 0 (layers 1-3): in = BN(d_agg)+ReLU (K=100), out -> d_m
#define MT 32
#define KC 50
__global__ void k_gemm(const float* __restrict__ W,
                       const float* __restrict__ bvec,
                       int K, int mode)
{
    __shared__ __align__(16) float Ws[KC][C];
    __shared__ float Hs[MT][KC + 2];

    const int tx  = threadIdx.x;          // 0..24
    const int ty  = threadIdx.y;          // 0..7
    const int tid = ty * 25 + tx;
    const int m0  = blockIdx.x * MT;

    float acc[4][4];
#pragma unroll
    for (int i = 0; i < 4; i++)
#pragma unroll
        for (int j = 0; j < 4; j++) acc[i][j] = 0.0f;

    for (int k0 = 0; k0 < K; k0 += KC) {
        const int kc = min(KC, K - k0);
        for (int idx = tid; idx < kc * C; idx += 200) {
            int kk = idx / C, cc = idx - kk * C;
            Ws[kk][cc] = W[(size_t)(k0 + kk) * C + cc];
        }
        for (int idx = tid; idx < MT * kc; idx += 200) {
            int rr = idx / kc, kk = idx - rr * kc;
            int r = m0 + rr;
            float v = 0.0f;
            if (r < NN) {
                int ch = k0 + kk;
                if (mode) {
                    v = d_aggx[(size_t)r * KIN + ch];
                } else {
                    v = d_agg[(size_t)r * C + ch];
                    v = fmaxf(fmaf(v, d_scale[ch], d_shift[ch]), 0.0f);
                }
            }
            Hs[rr][kk] = v;
        }
        __syncthreads();

        for (int k = 0; k < kc; k++) {
            float4 w4 = *(const float4*)&Ws[k][tx * 4];
#pragma unroll
            for (int i = 0; i < 4; i++) {
                float a = Hs[ty * 4 + i][k];
                acc[i][0] = fmaf(a, w4.x, acc[i][0]);
                acc[i][1] = fmaf(a, w4.y, acc[i][1]);
                acc[i][2] = fmaf(a, w4.z, acc[i][2]);
                acc[i][3] = fmaf(a, w4.w, acc[i][3]);
            }
        }
        __syncthreads();
    }

    const int c0 = tx * 4;
    if (mode) {
        const float4 b4 = *(const float4*)&bvec[c0];
#pragma unroll
        for (int i = 0; i < 4; i++) {
            int r = m0 + ty * 4 + i;
            if (r < NN)
                *(float4*)&d_agg[(size_t)r * C + c0] =
                    make_float4(acc[i][0] + b4.x, acc[i][1] + b4.y,
                                acc[i][2] + b4.z, acc[i][3] + b4.w);
        }
    } else {
#pragma unroll
        for (int i = 0; i < 4; i++) {
            int r = m0 + ty * 4 + i;
            if (r < NN)
                *(float4*)&d_m[(size_t)r * C + c0] =
                    make_float4(acc[i][0], acc[i][1], acc[i][2], acc[i][3]);
        }
    }
}

// ---------------- gather (layers 1-3): independent warps, no barriers ----------------
// agg[node] = dinv^2*m[node] + b + sum_e w*m[src]
__global__ void k_gather(const float* __restrict__ bvec) {
    int warp = (blockIdx.x * blockDim.x + threadIdx.x) >> 5;
    int lane = threadIdx.x & 31;
    if (warp >= NN) return;
    const int beg = d_row[warp], end = d_row[warp + 1];
    const bool active = lane < 25;
    float4 acc = make_float4(0.f, 0.f, 0.f, 0.f);
    if (active) {
        float dv = d_dinv[warp];
        float d2 = dv * dv;
        const float4 mv = *(const float4*)&d_m[(size_t)warp * C + lane * 4];
        const float4 b4 = *(const float4*)&bvec[lane * 4];
        acc = make_float4(fmaf(d2, mv.x, b4.x), fmaf(d2, mv.y, b4.y),
                          fmaf(d2, mv.z, b4.z), fmaf(d2, mv.w, b4.w));
    }
    int e = beg;
    for (; e + 1 < end; e += 2) {
        unsigned long long v0 = d_e[e], v1 = d_e[e + 1];
        int s0 = (int)(unsigned)v0, s1 = (int)(unsigned)v1;
        float w0 = __uint_as_float((unsigned)(v0 >> 32));
        float w1 = __uint_as_float((unsigned)(v1 >> 32));
        if (active) {
            const float4 a0 = *(const float4*)&d_m[(size_t)s0 * C + lane * 4];
            const float4 a1 = *(const float4*)&d_m[(size_t)s1 * C + lane * 4];
            acc.x = fmaf(w0, a0.x, acc.x); acc.y = fmaf(w0, a0.y, acc.y);
            acc.z = fmaf(w0, a0.z, acc.z); acc.w = fmaf(w0, a0.w, acc.w);
            acc.x = fmaf(w1, a1.x, acc.x); acc.y = fmaf(w1, a1.y, acc.y);
            acc.z = fmaf(w1, a1.z, acc.z); acc.w = fmaf(w1, a1.w, acc.w);
        }
    }
    if (e < end) {
        unsigned long long v0 = d_e[e];
        int s0 = (int)(unsigned)v0;
        float w0 = __uint_as_float((unsigned)(v0 >> 32));
        if (active) {
            const float4 a0 = *(const float4*)&d_m[(size_t)s0 * C + lane * 4];
            acc.x = fmaf(w0, a0.x, acc.x); acc.y = fmaf(w0, a0.y, acc.y);
            acc.z = fmaf(w0, a0.z, acc.z); acc.w = fmaf(w0, a0.w, acc.w);
        }
    }
    if (active) *(float4*)&d_agg[(size_t)warp * C + lane * 4] = acc;
}

// ---------------- BN statistics (two-stage, deterministic) ----------------
#define ROWS_PER_BLOCK 512
__global__ void k_stats() {
    int c  = threadIdx.x;   // 0..99
    int ty = threadIdx.y;   // 0..3
    int r0 = blockIdx.x * ROWS_PER_BLOCK;
    int rend = min(r0 + ROWS_PER_BLOCK, NN);
    float s = 0.0f, q = 0.0f;
    for (int r = r0 + ty; r < rend; r += 4) {
        float v = d_agg[(size_t)r * C + c];
        s += v;
        q = fmaf(v, v, q);
    }
    __shared__ float sh_s[4][C], sh_q[4][C];
    sh_s[ty][c] = s;
    sh_q[ty][c] = q;
    __syncthreads();
    if (ty == 0) {
        d_psum[blockIdx.x * C + c] = sh_s[0][c] + sh_s[1][c] + sh_s[2][c] + sh_s[3][c];
        d_psq [blockIdx.x * C + c] = sh_q[0][c] + sh_q[1][c] + sh_q[2][c] + sh_q[3][c];
    }
}

__global__ void k_finalize(const float* __restrict__ gamma,
                           const float* __restrict__ beta) {
    int c = threadIdx.x;
    if (c >= C) return;
    float S = 0.0f, Q = 0.0f;
    for (int bkt = 0; bkt < SGRID; bkt++) {
        S += d_psum[bkt * C + c];
        Q += d_psq [bkt * C + c];
    }
    float mean = S * (1.0f / (float)NN);
    float var  = Q * (1.0f / (float)NN) - mean * mean;
    float rstd = rsqrtf(var + BN_EPS);
    float sc = rstd * gamma[c];
    d_scale[c] = sc;
    d_shift[c] = beta[c] - mean * sc;
}

// ---------------- fused pool + output head ----------------
__global__ void k_poolout(const float* __restrict__ Wout,
                          const float* __restrict__ bout,
                          float* __restrict__ out) {
    __shared__ float pool[C];
    const int g = blockIdx.x;
    const int t = threadIdx.x;        // 0..199
    const int r0 = d_gstart[g], r1 = d_gstart[g + 1];
    if (t < C) {
        float s = 0.0f;
        for (int r = r0; r < r1; r++) s += d_agg[(size_t)r * C + t];
        pool[t] = fmaf(d_scale[t], s, (float)(r1 - r0) * d_shift[t]);
    }
    __syncthreads();
    float acc = bout[t];
#pragma unroll 4
    for (int k = 0; k < C; k++)
        acc = fmaf(pool[k], Wout[(size_t)k * OUTC + t], acc);
    out[(size_t)g * OUTC + t] = acc > 0.0f ? acc : 0.1f * acc;
}

// ---------------- launch ----------------
extern "C" void kernel_launch(void* const* d_in, const int* in_sizes, int n_in,
                              void* d_out, int out_size) {
    const float *x = 0, *W0 = 0, *Wrest = 0, *bb = 0, *gamma = 0, *beta = 0,
                *Wout = 0, *bout = 0;
    const void *ei = 0, *batch = 0;
    for (int i = 0; i < n_in; i++) {
        switch (in_sizes[i]) {
            case 1650000: x     = (const float*)d_in[i]; break;
            case 1600000: ei    = d_in[i];               break;
            case 50000:   batch = d_in[i];               break;
            case 3300:    W0    = (const float*)d_in[i]; break;
            case 30000:   Wrest = (const float*)d_in[i]; break;
            case 20000:   Wout  = (const float*)d_in[i]; break;
            case 200:     bout  = (const float*)d_in[i]; break;
            case 400:
                if (!bb) bb = (const float*)d_in[i];
                else if (!gamma) gamma = (const float*)d_in[i];
                else beta = (const float*)d_in[i];
                break;
            default: break;
        }
    }
    if (!x)     x     = (const float*)d_in[0];
    if (!ei)    ei    = d_in[1];
    if (!batch) batch = d_in[2];
    if (!W0)    W0    = (const float*)d_in[3];
    if (!Wrest) Wrest = (const float*)d_in[4];
    if (!bb)    bb    = (const float*)d_in[5];
    if (!gamma) gamma = (const float*)d_in[6];
    if (!beta)  beta  = (const float*)d_in[7];
    if (!Wout)  Wout  = (const float*)d_in[8];
    if (!bout)  bout  = (const float*)d_in[9];
    float* out = (float*)d_out;

    k_detect<<<1, 1>>>((const long long*)ei);
    k_indeg_zero<<<(NN + 255) / 256, 256>>>();
    k_prep_edges<<<(EE + 255) / 256, 256>>>(ei);
    k_convert_batch<<<(NN + 255) / 256, 256>>>(batch);
    k_scan<<<1, 1024>>>();
    k_dinv<<<(NN + 255) / 256, 256>>>();
    k_fill<<<(EE + 255) / 256, 256>>>();
    k_bounds<<<2, 512>>>();

    const dim3 gemm_blk(25, 8);
    const int gemm_grid = (NN + MT - 1) / MT;
    const int gather_grid = (NN * 32 + 255) / 256;
    const dim3 stats_blk(C, 4);

    // layer 0: aggregate x, then GEMM K=33 (+bias) -> agg, stats
    k_gatherX<<<(NN * 32 + 255) / 256, 256>>>(x);
    k_gemm<<<gemm_grid, gemm_blk>>>(W0, bb, KIN, 1);
    k_stats<<<SGRID, stats_blk>>>();
    k_finalize<<<1, 128>>>(gamma, beta);

    // layers 1-3
    for (int L = 1; L < 4; L++) {
        const float* W = Wrest + (size_t)(L - 1) * C * C;
        k_gemm<<<gemm_grid, gemm_blk>>>(W, 0, C, 0);
        k_gather<<<gather_grid, 256>>>(bb + L * C);
        k_stats<<<SGRID, stats_blk>>>();
        k_finalize<<<1, 128>>>(gamma + L * C, beta + L * C);
    }

    k_poolout<<<NG, OUTC>>>(Wout, bout, out);
}